// round 10
// baseline (speedup 1.0000x reference)
#include <cuda_runtime.h>
#include <cuda_bf16.h>
#include <cstdint>

typedef unsigned long long ull;
typedef unsigned int uint;

#define BB 16
#define CC 64
#define NN 4096      // H*W
#define NP 1024      // pooled positions
#define L2E 1.4426950408889634f

// ---------------- scratch (device globals; no allocation) ----------------
__device__ __nv_bfloat16 g_theta_b[BB * NN * 8];   // [b][n][8]   bf16, pre-scaled by log2e
__device__ __nv_bfloat16 g_phi_b[BB * NP * 8];     // [b][p][8]   bf16
__device__ __nv_bfloat16 g_gT_b[BB * 32 * NP];     // [b][ch][p]  bf16 (transposed)

// ---------------- f32x2 / misc helpers ----------------
__device__ __forceinline__ ull pack2(float lo, float hi) {
    ull r; asm("mov.b64 %0, {%1,%2};" : "=l"(r) : "f"(lo), "f"(hi)); return r;
}
__device__ __forceinline__ void unpack2(ull v, float& lo, float& hi) {
    asm("mov.b64 {%0,%1}, %2;" : "=f"(lo), "=f"(hi) : "l"(v));
}
__device__ __forceinline__ void fma2(ull& d, ull a, ull b) {
    asm("fma.rn.f32x2 %0, %1, %2, %0;" : "+l"(d) : "l"(a), "l"(b));
}
__device__ __forceinline__ ull mul2(ull a, ull b) {
    ull d; asm("mul.rn.f32x2 %0, %1, %2;" : "=l"(d) : "l"(a), "l"(b)); return d;
}
__device__ __forceinline__ float ex2f(float x) {
    float r; asm("ex2.approx.f32 %0, %1;" : "=f"(r) : "f"(x)); return r;
}
// pack two f32 -> bf16x2 (first arg -> low half)
__device__ __forceinline__ uint bf2(float lo, float hi) {
    uint r; asm("cvt.rn.bf16x2.f32 %0, %1, %2;" : "=r"(r) : "f"(hi), "f"(lo)); return r;
}
__device__ __forceinline__ float shflx(float v, int m) {
    float r; asm("shfl.sync.bfly.b32 %0, %1, %2, 0x1F, 0xFFFFFFFF;" : "=f"(r) : "f"(v), "r"(m));
    return r;
}

// ---------------- mma.sync (base sm_80+ feature; OK on plain sm_100) -----
__device__ __forceinline__ void mma_16n8k8(float d[4], const uint a[2], uint b) {
    asm volatile(
        "mma.sync.aligned.m16n8k8.row.col.f32.bf16.bf16.f32 "
        "{%0,%1,%2,%3}, {%4,%5}, {%6}, {%0,%1,%2,%3};"
        : "+f"(d[0]), "+f"(d[1]), "+f"(d[2]), "+f"(d[3])
        : "r"(a[0]), "r"(a[1]), "r"(b));
}
__device__ __forceinline__ void mma_16n8k16(float d[4], const uint a[4], uint b0, uint b1) {
    asm volatile(
        "mma.sync.aligned.m16n8k16.row.col.f32.bf16.bf16.f32 "
        "{%0,%1,%2,%3}, {%4,%5,%6,%7}, {%8,%9}, {%0,%1,%2,%3};"
        : "+f"(d[0]), "+f"(d[1]), "+f"(d[2]), "+f"(d[3])
        : "r"(a[0]), "r"(a[1]), "r"(a[2]), "r"(a[3]), "r"(b0), "r"(b1));
}

// =========================================================================
// Kernel 1: 1x1 conv projections + 2x2 maxpool -> bf16 outputs.
// =========================================================================
__global__ void __launch_bounds__(128, 1)
proj_kernel(const float* __restrict__ x,
            const float* __restrict__ tw,
            const float* __restrict__ pw,
            const float* __restrict__ gw)
{
    __shared__ float ws[64 * 48];
    for (int i = threadIdx.x; i < 64 * 48; i += 128) {
        int k = i / 48, o = i % 48;
        float v;
        if (o < 8)        v = tw[o * 64 + k];
        else if (o < 16)  v = pw[(o - 8) * 64 + k];
        else              v = gw[(o - 16) * 64 + k];
        ws[i] = v;
    }
    __syncthreads();

    int p  = blockIdx.x * 128 + threadIdx.x;
    int b  = p >> 10;
    int pp = p & 1023;
    int hp = pp >> 5, wp = pp & 31;

    const float* xb = x + (size_t)b * CC * NN;

    float best[40];
#pragma unroll
    for (int c = 0; c < 40; c++) best[c] = -1e30f;

    for (int dy = 0; dy < 2; dy++) {
        ull acc0[24], acc1[24];
#pragma unroll
        for (int c = 0; c < 24; c++) { acc0[c] = 0ull; acc1[c] = 0ull; }

        const float* xrow = xb + (2 * hp + dy) * 64 + 2 * wp;
#pragma unroll 4
        for (int k = 0; k < 64; k++) {
            float2 xv = *(const float2*)(xrow + (size_t)k * NN);
            ull a0 = pack2(xv.x, xv.x);
            ull a1 = pack2(xv.y, xv.y);
            const ull* w2 = (const ull*)(ws + k * 48);
#pragma unroll
            for (int c = 0; c < 24; c++) {
                ull w = w2[c];
                fma2(acc0[c], a0, w);
                fma2(acc1[c], a1, w);
            }
        }

        int n0 = (2 * hp + dy) * 64 + 2 * wp;
        {   // theta -> bf16 pre-scaled by log2(e)
            float u, v; uint4 q;
            unpack2(acc0[0], u, v); q.x = bf2(u * L2E, v * L2E);
            unpack2(acc0[1], u, v); q.y = bf2(u * L2E, v * L2E);
            unpack2(acc0[2], u, v); q.z = bf2(u * L2E, v * L2E);
            unpack2(acc0[3], u, v); q.w = bf2(u * L2E, v * L2E);
            *(uint4*)(g_theta_b + ((size_t)b * NN + n0) * 8) = q;
            unpack2(acc1[0], u, v); q.x = bf2(u * L2E, v * L2E);
            unpack2(acc1[1], u, v); q.y = bf2(u * L2E, v * L2E);
            unpack2(acc1[2], u, v); q.z = bf2(u * L2E, v * L2E);
            unpack2(acc1[3], u, v); q.w = bf2(u * L2E, v * L2E);
            *(uint4*)(g_theta_b + ((size_t)b * NN + n0 + 1) * 8) = q;
        }
#pragma unroll
        for (int c = 4; c < 24; c++) {
            float u, v;
            unpack2(acc0[c], u, v);
            best[2 * c - 8]     = fmaxf(best[2 * c - 8], u);
            best[2 * c - 8 + 1] = fmaxf(best[2 * c - 8 + 1], v);
            unpack2(acc1[c], u, v);
            best[2 * c - 8]     = fmaxf(best[2 * c - 8], u);
            best[2 * c - 8 + 1] = fmaxf(best[2 * c - 8 + 1], v);
        }
    }

    {   // phi bf16 [b][pp][8]
        uint4 q;
        q.x = bf2(best[0], best[1]); q.y = bf2(best[2], best[3]);
        q.z = bf2(best[4], best[5]); q.w = bf2(best[6], best[7]);
        *(uint4*)(g_phi_b + ((size_t)b * NP + pp) * 8) = q;
    }
    {   // g transposed bf16 [b][ch][pp]
#pragma unroll
        for (int c = 0; c < 32; c++)
            g_gT_b[((size_t)b * 32 + c) * NP + pp] = __float2bfloat16(best[8 + c]);
    }
}

// =========================================================================
// Kernel 2: mma.sync flash attention + o-projection + residual.
// Grid (8 tiles, 16 batches), 512 threads (16 warps = 4/SMSP for latency).
// Warp owns 32 queries (2 m16 tiles); loops 64 chunks of 16 keys:
//   GEMM1 m16n8k8:  S(16qx8k) = theta x phi   (K = 8 channels, exact)
//   softmax: ex2 -> den, pack c-frag -> a-frag (FA2 identity)
//   GEMM2 m16n8k16: A(16qx8ch) += P x gT      (g pre-packed b-frag order)
// Then attn -> smem, f32x2 o_w epilogue (1 query/thread) + residual.
// =========================================================================
#define THREADS 512
#define NQT 2
#define SM_PHI   0                    // 1024 x 16B bf16        = 16384
#define SM_GB    16384                // 64kc x 4nt x 32 x 8B   = 65536
#define SM_OW    (16384 + 65536)      // 64 x 32 f32            = 8192
#define SM_DEN   (16384 + 65536 + 8192)            // 512 f32   = 2048
#define SM_ATT   (16384 + 65536 + 8192 + 2048)     // 512 x 34 f32 = 69632
#define SMEM_BYTES (16384 + 65536 + 8192 + 2048 + 69632)
#define ATT_STRIDE 34

__global__ void __launch_bounds__(THREADS, 1)
attn_kernel(const float* __restrict__ x,
            const float* __restrict__ ow,
            const float* __restrict__ gamma_p,
            float* __restrict__ out)
{
    extern __shared__ char sm[];
    const int tid  = threadIdx.x;
    const int wid  = tid >> 5;
    const int lane = tid & 31;
    const int g    = lane >> 2;      // groupID
    const int tig  = lane & 3;       // thread-in-group
    const int b    = blockIdx.y;
    const int tile = blockIdx.x;

    // ---- stage phi [key][8ch] bf16 ----
    {
        const uint4* src = (const uint4*)(g_phi_b + (size_t)b * NP * 8);
        uint4* dst = (uint4*)(sm + SM_PHI);
        for (int i = tid; i < 1024; i += THREADS) dst[i] = src[i];
    }
    // ---- stage gB in b-frag order: [kc][nt][lane] = (b0|b1<<32) ----
    {
        const __nv_bfloat16* gT = g_gT_b + (size_t)b * 32 * NP;
        ull* dst = (ull*)(sm + SM_GB);
        for (int idx = tid; idx < 64 * 4 * 32; idx += THREADS) {
            int ln = idx & 31, nt = (idx >> 5) & 3, kc = idx >> 7;
            int ch = nt * 8 + (ln >> 2);
            const __nv_bfloat16* row = gT + (size_t)ch * NP + kc * 16 + 2 * (ln & 3);
            uint lo = *(const uint*)row;        // keys 2tig, 2tig+1
            uint hi = *(const uint*)(row + 8);  // keys 2tig+8, 2tig+9
            dst[idx] = (ull)lo | ((ull)hi << 32);
        }
    }
    // ---- stage ow (f32) ----
    {
        const float4* src = (const float4*)ow;
        float4* dst = (float4*)(sm + SM_OW);
        for (int i = tid; i < 512; i += THREADS) dst[i] = src[i];
    }
    __syncthreads();

    // ---- theta a-frags: NQT q-tiles of 16 rows ----
    const int wq = tile * 512 + wid * (16 * NQT);  // warp's first query (global n)
    uint ta[NQT][2];
#pragma unroll
    for (int qt = 0; qt < NQT; qt++) {
        const __nv_bfloat16* t0 = g_theta_b + ((size_t)b * NN + wq + qt * 16 + g) * 8 + 2 * tig;
        ta[qt][0] = *(const uint*)t0;
        ta[qt][1] = *(const uint*)(t0 + 64);   // row +8 -> +8*8 elements
    }

    float aoc[NQT][4][4];
#pragma unroll
    for (int qt = 0; qt < NQT; qt++)
#pragma unroll
        for (int nt = 0; nt < 4; nt++)
#pragma unroll
            for (int r = 0; r < 4; r++) aoc[qt][nt][r] = 0.f;
    float dn[NQT][2];
#pragma unroll
    for (int qt = 0; qt < NQT; qt++) { dn[qt][0] = 0.f; dn[qt][1] = 0.f; }

    const char* phiS = sm + SM_PHI;
    const ull*  gB   = (const ull*)(sm + SM_GB);

    for (int kc = 0; kc < 64; kc++) {
        uint pa[NQT][4];
        // GEMM1 + softmax for the two 8-key subtiles
#pragma unroll
        for (int kb = 0; kb < 2; kb++) {
            uint pb = *(const uint*)(phiS + (kc * 16 + kb * 8 + g) * 16 + tig * 4);
#pragma unroll
            for (int qt = 0; qt < NQT; qt++) {
                float s[4] = {0.f, 0.f, 0.f, 0.f};
                mma_16n8k8(s, ta[qt], pb);
                float e0 = ex2f(s[0]), e1 = ex2f(s[1]);
                float e2 = ex2f(s[2]), e3 = ex2f(s[3]);
                dn[qt][0] += e0 + e1;
                dn[qt][1] += e2 + e3;
                pa[qt][kb * 2 + 0] = bf2(e0, e1);   // (q=g,   k=2tig..+1)
                pa[qt][kb * 2 + 1] = bf2(e2, e3);   // (q=g+8, k=2tig..+1)
            }
        }
        // GEMM2: A += P x gT
#pragma unroll
        for (int nt = 0; nt < 4; nt++) {
            ull bb = gB[(kc * 4 + nt) * 32 + lane];
            uint b0 = (uint)bb, b1 = (uint)(bb >> 32);
#pragma unroll
            for (int qt = 0; qt < NQT; qt++)
                mma_16n8k16(aoc[qt][nt], pa[qt], b0, b1);
        }
    }

    // ---- den reduce (over tig lanes) + store attn/den to smem ----
    float* denS = (float*)(sm + SM_DEN);
    float* attS = (float*)(sm + SM_ATT);
    const int wqp = wid * (16 * NQT);          // warp's query offset within tile
#pragma unroll
    for (int qt = 0; qt < NQT; qt++) {
        float d0 = dn[qt][0]; d0 += shflx(d0, 1); d0 += shflx(d0, 2);
        float d1 = dn[qt][1]; d1 += shflx(d1, 1); d1 += shflx(d1, 2);
        if (tig == 0) {
            denS[wqp + qt * 16 + g]     = d0;
            denS[wqp + qt * 16 + g + 8] = d1;
        }
#pragma unroll
        for (int nt = 0; nt < 4; nt++) {
            int q0 = wqp + qt * 16 + g;
            int ch = nt * 8 + 2 * tig;
            *(float2*)(attS + (size_t)q0 * ATT_STRIDE + ch) =
                make_float2(aoc[qt][nt][0], aoc[qt][nt][1]);
            *(float2*)(attS + (size_t)(q0 + 8) * ATT_STRIDE + ch) =
                make_float2(aoc[qt][nt][2], aoc[qt][nt][3]);
        }
    }
    __syncthreads();

    // ---- epilogue: o = ow x attn ; out = (gamma/den) * o + x ----
    const float gamma = *gamma_p;
    const ulonglong2* ow4 = (const ulonglong2*)(sm + SM_OW);   // [j][8]
    {
        const int p = tid;                          // query within tile [0,512)
        ull am[16];
        const ull* ap = (const ull*)(attS + (size_t)p * ATT_STRIDE);
#pragma unroll
        for (int c = 0; c < 16; c++) am[c] = ap[c];
        const float sc = gamma / denS[p];

        const int q = tile * 512 + p;
        const float* xq = x + (size_t)b * CC * NN + q;
        float*       oq = out + (size_t)b * CC * NN + q;
        for (int j = 0; j < 64; j++) {
            const ulonglong2* wj = ow4 + j * 8;
            ulonglong2 w0 = wj[0];
            ull o2 = mul2(w0.x, am[0]);
            fma2(o2, w0.y, am[1]);
#pragma unroll
            for (int k = 1; k < 8; k++) {
                ulonglong2 wk = wj[k];
                fma2(o2, wk.x, am[2 * k]);
                fma2(o2, wk.y, am[2 * k + 1]);
            }
            float oa, ob;
            unpack2(o2, oa, ob);
            oq[(size_t)j * NN] = fmaf(sc, oa + ob, xq[(size_t)j * NN]);
        }
    }
}

// =========================================================================
extern "C" void kernel_launch(void* const* d_in, const int* in_sizes, int n_in,
                              void* d_out, int out_size)
{
    const float* x     = (const float*)d_in[0];
    const float* tw    = (const float*)d_in[1];
    const float* pw    = (const float*)d_in[2];
    const float* gw    = (const float*)d_in[3];
    const float* ow    = (const float*)d_in[4];
    const float* gamma = (const float*)d_in[5];
    float* out = (float*)d_out;

    cudaFuncSetAttribute(attn_kernel,
                         cudaFuncAttributeMaxDynamicSharedMemorySize, SMEM_BYTES);

    proj_kernel<<<BB * NP / 128, 128>>>(x, tw, pw, gw);
    attn_kernel<<<dim3(8, BB), THREADS, SMEM_BYTES>>>(x, ow, gamma, out);
}

// round 11
// speedup vs baseline: 1.0722x; 1.0722x over previous
#include <cuda_runtime.h>
#include <cuda_bf16.h>
#include <cstdint>

typedef unsigned long long ull;
typedef unsigned int uint;

#define BB 16
#define CC 64
#define NN 4096      // H*W
#define NP 1024      // pooled positions
#define L2E 1.4426950408889634f

// ---------------- scratch (device globals; no allocation) ----------------
__device__ __nv_bfloat16 g_theta_b[BB * NN * 8];   // [b][n][8]   bf16, pre-scaled by log2e
__device__ __nv_bfloat16 g_phi_b[BB * NP * 8];     // [b][p][8]   bf16
__device__ __nv_bfloat16 g_gT_b[BB * 32 * NP];     // [b][ch][p]  bf16 (transposed)

// ---------------- f32x2 / misc helpers ----------------
__device__ __forceinline__ ull pack2(float lo, float hi) {
    ull r; asm("mov.b64 %0, {%1,%2};" : "=l"(r) : "f"(lo), "f"(hi)); return r;
}
__device__ __forceinline__ void unpack2(ull v, float& lo, float& hi) {
    asm("mov.b64 {%0,%1}, %2;" : "=f"(lo), "=f"(hi) : "l"(v));
}
__device__ __forceinline__ void fma2(ull& d, ull a, ull b) {
    asm("fma.rn.f32x2 %0, %1, %2, %0;" : "+l"(d) : "l"(a), "l"(b));
}
__device__ __forceinline__ ull mul2(ull a, ull b) {
    ull d; asm("mul.rn.f32x2 %0, %1, %2;" : "=l"(d) : "l"(a), "l"(b)); return d;
}
__device__ __forceinline__ float ex2f(float x) {
    float r; asm("ex2.approx.f32 %0, %1;" : "=f"(r) : "f"(x)); return r;
}
// pack two f32 -> bf16x2 (first arg -> low half)
__device__ __forceinline__ uint bf2(float lo, float hi) {
    uint r; asm("cvt.rn.bf16x2.f32 %0, %1, %2;" : "=r"(r) : "f"(hi), "f"(lo)); return r;
}
__device__ __forceinline__ float shflx(float v, int m) {
    float r; asm("shfl.sync.bfly.b32 %0, %1, %2, 0x1F, 0xFFFFFFFF;" : "=f"(r) : "f"(v), "r"(m));
    return r;
}

// ---------------- mma.sync (base sm_80+ feature; OK on plain sm_100) -----
__device__ __forceinline__ void mma_16n8k8(float d[4], const uint a[2], uint b) {
    asm volatile(
        "mma.sync.aligned.m16n8k8.row.col.f32.bf16.bf16.f32 "
        "{%0,%1,%2,%3}, {%4,%5}, {%6}, {%0,%1,%2,%3};"
        : "+f"(d[0]), "+f"(d[1]), "+f"(d[2]), "+f"(d[3])
        : "r"(a[0]), "r"(a[1]), "r"(b));
}
__device__ __forceinline__ void mma_16n8k16(float d[4], const uint a[4], uint b0, uint b1) {
    asm volatile(
        "mma.sync.aligned.m16n8k16.row.col.f32.bf16.bf16.f32 "
        "{%0,%1,%2,%3}, {%4,%5,%6,%7}, {%8,%9}, {%0,%1,%2,%3};"
        : "+f"(d[0]), "+f"(d[1]), "+f"(d[2]), "+f"(d[3])
        : "r"(a[0]), "r"(a[1]), "r"(a[2]), "r"(a[3]), "r"(b0), "r"(b1));
}

// =========================================================================
// Kernel 1: 1x1 conv projections + 2x2 maxpool -> bf16 outputs.
// 256 threads: thread = (pooled position, dy). Pairs of adjacent lanes
// combine the 2x2 maxpool via shfl.xor 1. dy=0 writes phi, dy=1 writes gT.
// =========================================================================
__global__ void __launch_bounds__(256, 1)
proj_kernel(const float* __restrict__ x,
            const float* __restrict__ tw,
            const float* __restrict__ pw,
            const float* __restrict__ gw)
{
    __shared__ float ws[64 * 48];
    for (int i = threadIdx.x; i < 64 * 48; i += 256) {
        int k = i / 48, o = i % 48;
        float v;
        if (o < 8)        v = tw[o * 64 + k];
        else if (o < 16)  v = pw[(o - 8) * 64 + k];
        else              v = gw[(o - 16) * 64 + k];
        ws[i] = v;
    }
    __syncthreads();

    const int tid = threadIdx.x;
    const int dy  = tid & 1;
    int p  = blockIdx.x * 128 + (tid >> 1);   // global pooled index
    int b  = p >> 10;
    int pp = p & 1023;
    int hp = pp >> 5, wp = pp & 31;

    const float* xb = x + (size_t)b * CC * NN;

    ull acc0[24], acc1[24];
#pragma unroll
    for (int c = 0; c < 24; c++) { acc0[c] = 0ull; acc1[c] = 0ull; }

    const float* xrow = xb + (2 * hp + dy) * 64 + 2 * wp;
#pragma unroll 4
    for (int k = 0; k < 64; k++) {
        float2 xv = *(const float2*)(xrow + (size_t)k * NN);
        ull a0 = pack2(xv.x, xv.x);
        ull a1 = pack2(xv.y, xv.y);
        const ull* w2 = (const ull*)(ws + k * 48);
#pragma unroll
        for (int c = 0; c < 24; c++) {
            ull w = w2[c];
            fma2(acc0[c], a0, w);
            fma2(acc1[c], a1, w);
        }
    }

    // theta write (this thread's row: 2 pixels), bf16 pre-scaled by log2(e)
    {
        int n0 = (2 * hp + dy) * 64 + 2 * wp;
        float u, v; uint4 q;
        unpack2(acc0[0], u, v); q.x = bf2(u * L2E, v * L2E);
        unpack2(acc0[1], u, v); q.y = bf2(u * L2E, v * L2E);
        unpack2(acc0[2], u, v); q.z = bf2(u * L2E, v * L2E);
        unpack2(acc0[3], u, v); q.w = bf2(u * L2E, v * L2E);
        *(uint4*)(g_theta_b + ((size_t)b * NN + n0) * 8) = q;
        unpack2(acc1[0], u, v); q.x = bf2(u * L2E, v * L2E);
        unpack2(acc1[1], u, v); q.y = bf2(u * L2E, v * L2E);
        unpack2(acc1[2], u, v); q.z = bf2(u * L2E, v * L2E);
        unpack2(acc1[3], u, v); q.w = bf2(u * L2E, v * L2E);
        *(uint4*)(g_theta_b + ((size_t)b * NN + n0 + 1) * 8) = q;
    }

    // pool within this row (2 pixels) -> best[40], then combine with partner
    float best[40];
#pragma unroll
    for (int c = 4; c < 24; c++) {
        float u0, v0, u1, v1;
        unpack2(acc0[c], u0, v0);
        unpack2(acc1[c], u1, v1);
        best[2 * c - 8]     = fmaxf(u0, u1);
        best[2 * c - 8 + 1] = fmaxf(v0, v1);
    }
#pragma unroll
    for (int c = 0; c < 40; c++)
        best[c] = fmaxf(best[c], shflx(best[c], 1));   // dy-partner = lane^1

    if (dy == 0) {   // phi bf16 [b][pp][8]
        uint4 q;
        q.x = bf2(best[0], best[1]); q.y = bf2(best[2], best[3]);
        q.z = bf2(best[4], best[5]); q.w = bf2(best[6], best[7]);
        *(uint4*)(g_phi_b + ((size_t)b * NP + pp) * 8) = q;
    } else {         // g transposed bf16 [b][ch][pp]
#pragma unroll
        for (int c = 0; c < 32; c++)
            g_gT_b[((size_t)b * 32 + c) * NP + pp] = __float2bfloat16(best[8 + c]);
    }
}

// =========================================================================
// Kernel 2: mma.sync flash attention + o-projection + residual.
// (unchanged from the 63.7us passing version)
// =========================================================================
#define THREADS 512
#define NQT 2
#define SM_PHI   0                    // 1024 x 16B bf16        = 16384
#define SM_GB    16384                // 64kc x 4nt x 32 x 8B   = 65536
#define SM_OW    (16384 + 65536)      // 64 x 32 f32            = 8192
#define SM_DEN   (16384 + 65536 + 8192)            // 512 f32   = 2048
#define SM_ATT   (16384 + 65536 + 8192 + 2048)     // 512 x 34 f32 = 69632
#define SMEM_BYTES (16384 + 65536 + 8192 + 2048 + 69632)
#define ATT_STRIDE 34

__global__ void __launch_bounds__(THREADS, 1)
attn_kernel(const float* __restrict__ x,
            const float* __restrict__ ow,
            const float* __restrict__ gamma_p,
            float* __restrict__ out)
{
    extern __shared__ char sm[];
    const int tid  = threadIdx.x;
    const int wid  = tid >> 5;
    const int lane = tid & 31;
    const int g    = lane >> 2;      // groupID
    const int tig  = lane & 3;       // thread-in-group
    const int b    = blockIdx.y;
    const int tile = blockIdx.x;

    // ---- stage phi [key][8ch] bf16 ----
    {
        const uint4* src = (const uint4*)(g_phi_b + (size_t)b * NP * 8);
        uint4* dst = (uint4*)(sm + SM_PHI);
        for (int i = tid; i < 1024; i += THREADS) dst[i] = src[i];
    }
    // ---- stage gB in b-frag order: [kc][nt][lane] = (b0|b1<<32) ----
    {
        const __nv_bfloat16* gT = g_gT_b + (size_t)b * 32 * NP;
        ull* dst = (ull*)(sm + SM_GB);
        for (int idx = tid; idx < 64 * 4 * 32; idx += THREADS) {
            int ln = idx & 31, nt = (idx >> 5) & 3, kc = idx >> 7;
            int ch = nt * 8 + (ln >> 2);
            const __nv_bfloat16* row = gT + (size_t)ch * NP + kc * 16 + 2 * (ln & 3);
            uint lo = *(const uint*)row;        // keys 2tig, 2tig+1
            uint hi = *(const uint*)(row + 8);  // keys 2tig+8, 2tig+9
            dst[idx] = (ull)lo | ((ull)hi << 32);
        }
    }
    // ---- stage ow (f32) ----
    {
        const float4* src = (const float4*)ow;
        float4* dst = (float4*)(sm + SM_OW);
        for (int i = tid; i < 512; i += THREADS) dst[i] = src[i];
    }
    __syncthreads();

    // ---- theta a-frags: NQT q-tiles of 16 rows ----
    const int wq = tile * 512 + wid * (16 * NQT);  // warp's first query (global n)
    uint ta[NQT][2];
#pragma unroll
    for (int qt = 0; qt < NQT; qt++) {
        const __nv_bfloat16* t0 = g_theta_b + ((size_t)b * NN + wq + qt * 16 + g) * 8 + 2 * tig;
        ta[qt][0] = *(const uint*)t0;
        ta[qt][1] = *(const uint*)(t0 + 64);   // row +8 -> +8*8 elements
    }

    float aoc[NQT][4][4];
#pragma unroll
    for (int qt = 0; qt < NQT; qt++)
#pragma unroll
        for (int nt = 0; nt < 4; nt++)
#pragma unroll
            for (int r = 0; r < 4; r++) aoc[qt][nt][r] = 0.f;
    float dn[NQT][2];
#pragma unroll
    for (int qt = 0; qt < NQT; qt++) { dn[qt][0] = 0.f; dn[qt][1] = 0.f; }

    const char* phiS = sm + SM_PHI;
    const ull*  gB   = (const ull*)(sm + SM_GB);

    for (int kc = 0; kc < 64; kc++) {
        uint pa[NQT][4];
        // GEMM1 + softmax for the two 8-key subtiles
#pragma unroll
        for (int kb = 0; kb < 2; kb++) {
            uint pb = *(const uint*)(phiS + (kc * 16 + kb * 8 + g) * 16 + tig * 4);
#pragma unroll
            for (int qt = 0; qt < NQT; qt++) {
                float s[4] = {0.f, 0.f, 0.f, 0.f};
                mma_16n8k8(s, ta[qt], pb);
                float e0 = ex2f(s[0]), e1 = ex2f(s[1]);
                float e2 = ex2f(s[2]), e3 = ex2f(s[3]);
                dn[qt][0] += e0 + e1;
                dn[qt][1] += e2 + e3;
                pa[qt][kb * 2 + 0] = bf2(e0, e1);   // (q=g,   k=2tig..+1)
                pa[qt][kb * 2 + 1] = bf2(e2, e3);   // (q=g+8, k=2tig..+1)
            }
        }
        // GEMM2: A += P x gT
#pragma unroll
        for (int nt = 0; nt < 4; nt++) {
            ull bb = gB[(kc * 4 + nt) * 32 + lane];
            uint b0 = (uint)bb, b1 = (uint)(bb >> 32);
#pragma unroll
            for (int qt = 0; qt < NQT; qt++)
                mma_16n8k16(aoc[qt][nt], pa[qt], b0, b1);
        }
    }

    // ---- den reduce (over tig lanes) + store attn/den to smem ----
    float* denS = (float*)(sm + SM_DEN);
    float* attS = (float*)(sm + SM_ATT);
    const int wqp = wid * (16 * NQT);          // warp's query offset within tile
#pragma unroll
    for (int qt = 0; qt < NQT; qt++) {
        float d0 = dn[qt][0]; d0 += shflx(d0, 1); d0 += shflx(d0, 2);
        float d1 = dn[qt][1]; d1 += shflx(d1, 1); d1 += shflx(d1, 2);
        if (tig == 0) {
            denS[wqp + qt * 16 + g]     = d0;
            denS[wqp + qt * 16 + g + 8] = d1;
        }
#pragma unroll
        for (int nt = 0; nt < 4; nt++) {
            int q0 = wqp + qt * 16 + g;
            int ch = nt * 8 + 2 * tig;
            *(float2*)(attS + (size_t)q0 * ATT_STRIDE + ch) =
                make_float2(aoc[qt][nt][0], aoc[qt][nt][1]);
            *(float2*)(attS + (size_t)(q0 + 8) * ATT_STRIDE + ch) =
                make_float2(aoc[qt][nt][2], aoc[qt][nt][3]);
        }
    }
    __syncthreads();

    // ---- epilogue: o = ow x attn ; out = (gamma/den) * o + x ----
    const float gamma = *gamma_p;
    const ulonglong2* ow4 = (const ulonglong2*)(sm + SM_OW);   // [j][8]
    {
        const int p = tid;                          // query within tile [0,512)
        ull am[16];
        const ull* ap = (const ull*)(attS + (size_t)p * ATT_STRIDE);
#pragma unroll
        for (int c = 0; c < 16; c++) am[c] = ap[c];
        const float sc = gamma / denS[p];

        const int q = tile * 512 + p;
        const float* xq = x + (size_t)b * CC * NN + q;
        float*       oq = out + (size_t)b * CC * NN + q;
        for (int j = 0; j < 64; j++) {
            const ulonglong2* wj = ow4 + j * 8;
            ulonglong2 w0 = wj[0];
            ull o2 = mul2(w0.x, am[0]);
            fma2(o2, w0.y, am[1]);
#pragma unroll
            for (int k = 1; k < 8; k++) {
                ulonglong2 wk = wj[k];
                fma2(o2, wk.x, am[2 * k]);
                fma2(o2, wk.y, am[2 * k + 1]);
            }
            float oa, ob;
            unpack2(o2, oa, ob);
            oq[(size_t)j * NN] = fmaf(sc, oa + ob, xq[(size_t)j * NN]);
        }
    }
}

// =========================================================================
extern "C" void kernel_launch(void* const* d_in, const int* in_sizes, int n_in,
                              void* d_out, int out_size)
{
    const float* x     = (const float*)d_in[0];
    const float* tw    = (const float*)d_in[1];
    const float* pw    = (const float*)d_in[2];
    const float* gw    = (const float*)d_in[3];
    const float* ow    = (const float*)d_in[4];
    const float* gamma = (const float*)d_in[5];
    float* out = (float*)d_out;

    cudaFuncSetAttribute(attn_kernel,
                         cudaFuncAttributeMaxDynamicSharedMemorySize, SMEM_BYTES);

    proj_kernel<<<BB * NP / 128, 256>>>(x, tw, pw, gw);
    attn_kernel<<<dim3(8, BB), THREADS, SMEM_BYTES>>>(x, ow, gamma, out);
}

// round 13
// speedup vs baseline: 1.1018x; 1.0277x over previous
#include <cuda_runtime.h>
#include <cuda_bf16.h>
#include <cstdint>

typedef unsigned long long ull;
typedef unsigned int uint;

#define BB 16
#define CC 64
#define NN 4096      // H*W
#define NP 1024      // pooled positions
#define L2E 1.4426950408889634f

// ---------------- scratch (device globals; no allocation) ----------------
__device__ __nv_bfloat16 g_theta_b[BB * NN * 8];   // [b][n][8]   bf16, pre-scaled by log2e
__device__ __nv_bfloat16 g_phi_b[BB * NP * 8];     // [b][p][8]   bf16
__device__ __nv_bfloat16 g_gT_b[BB * 32 * NP];     // [b][ch][p]  bf16 (transposed)

// ---------------- f32x2 / misc helpers ----------------
__device__ __forceinline__ ull pack2(float lo, float hi) {
    ull r; asm("mov.b64 %0, {%1,%2};" : "=l"(r) : "f"(lo), "f"(hi)); return r;
}
__device__ __forceinline__ void unpack2(ull v, float& lo, float& hi) {
    asm("mov.b64 {%0,%1}, %2;" : "=f"(lo), "=f"(hi) : "l"(v));
}
__device__ __forceinline__ void fma2(ull& d, ull a, ull b) {
    asm("fma.rn.f32x2 %0, %1, %2, %0;" : "+l"(d) : "l"(a), "l"(b));
}
__device__ __forceinline__ ull mul2(ull a, ull b) {
    ull d; asm("mul.rn.f32x2 %0, %1, %2;" : "=l"(d) : "l"(a), "l"(b)); return d;
}
__device__ __forceinline__ float ex2f(float x) {
    float r; asm("ex2.approx.f32 %0, %1;" : "=f"(r) : "f"(x)); return r;
}
// pack two f32 -> bf16x2 (first arg -> low half)
__device__ __forceinline__ uint bf2(float lo, float hi) {
    uint r; asm("cvt.rn.bf16x2.f32 %0, %1, %2;" : "=r"(r) : "f"(hi), "f"(lo)); return r;
}
__device__ __forceinline__ float shflx(float v, int m) {
    float r; asm("shfl.sync.bfly.b32 %0, %1, %2, 0x1F, 0xFFFFFFFF;" : "=f"(r) : "f"(v), "r"(m));
    return r;
}

// ---------------- mma.sync (base sm_80+ feature; OK on plain sm_100) -----
__device__ __forceinline__ void mma_16n8k8(float d[4], const uint a[2], uint b) {
    asm volatile(
        "mma.sync.aligned.m16n8k8.row.col.f32.bf16.bf16.f32 "
        "{%0,%1,%2,%3}, {%4,%5}, {%6}, {%0,%1,%2,%3};"
        : "+f"(d[0]), "+f"(d[1]), "+f"(d[2]), "+f"(d[3])
        : "r"(a[0]), "r"(a[1]), "r"(b));
}
__device__ __forceinline__ void mma_16n8k16(float d[4], const uint a[4], uint b0, uint b1) {
    asm volatile(
        "mma.sync.aligned.m16n8k16.row.col.f32.bf16.bf16.f32 "
        "{%0,%1,%2,%3}, {%4,%5,%6,%7}, {%8,%9}, {%0,%1,%2,%3};"
        : "+f"(d[0]), "+f"(d[1]), "+f"(d[2]), "+f"(d[3])
        : "r"(a[0]), "r"(a[1]), "r"(a[2]), "r"(a[3]), "r"(b0), "r"(b1));
}

// =========================================================================
// Kernel 1: 1x1 conv projections + 2x2 maxpool -> bf16 outputs.
// 256 threads: thread = (pooled position, dy). Pairs of adjacent lanes
// combine the 2x2 maxpool via shfl.xor 1. dy=0 writes phi, dy=1 writes gT.
// =========================================================================
__global__ void __launch_bounds__(256, 1)
proj_kernel(const float* __restrict__ x,
            const float* __restrict__ tw,
            const float* __restrict__ pw,
            const float* __restrict__ gw)
{
    __shared__ float ws[64 * 48];
    for (int i = threadIdx.x; i < 64 * 48; i += 256) {
        int k = i / 48, o = i % 48;
        float v;
        if (o < 8)        v = tw[o * 64 + k];
        else if (o < 16)  v = pw[(o - 8) * 64 + k];
        else              v = gw[(o - 16) * 64 + k];
        ws[i] = v;
    }
    __syncthreads();

    const int tid = threadIdx.x;
    const int dy  = tid & 1;
    int p  = blockIdx.x * 128 + (tid >> 1);   // global pooled index
    int b  = p >> 10;
    int pp = p & 1023;
    int hp = pp >> 5, wp = pp & 31;

    const float* xb = x + (size_t)b * CC * NN;

    ull acc0[24], acc1[24];
#pragma unroll
    for (int c = 0; c < 24; c++) { acc0[c] = 0ull; acc1[c] = 0ull; }

    const float* xrow = xb + (2 * hp + dy) * 64 + 2 * wp;
#pragma unroll 4
    for (int k = 0; k < 64; k++) {
        float2 xv = *(const float2*)(xrow + (size_t)k * NN);
        ull a0 = pack2(xv.x, xv.x);
        ull a1 = pack2(xv.y, xv.y);
        const ull* w2 = (const ull*)(ws + k * 48);
#pragma unroll
        for (int c = 0; c < 24; c++) {
            ull w = w2[c];
            fma2(acc0[c], a0, w);
            fma2(acc1[c], a1, w);
        }
    }

    // theta write (this thread's row: 2 pixels), bf16 pre-scaled by log2(e)
    {
        int n0 = (2 * hp + dy) * 64 + 2 * wp;
        float u, v; uint4 q;
        unpack2(acc0[0], u, v); q.x = bf2(u * L2E, v * L2E);
        unpack2(acc0[1], u, v); q.y = bf2(u * L2E, v * L2E);
        unpack2(acc0[2], u, v); q.z = bf2(u * L2E, v * L2E);
        unpack2(acc0[3], u, v); q.w = bf2(u * L2E, v * L2E);
        *(uint4*)(g_theta_b + ((size_t)b * NN + n0) * 8) = q;
        unpack2(acc1[0], u, v); q.x = bf2(u * L2E, v * L2E);
        unpack2(acc1[1], u, v); q.y = bf2(u * L2E, v * L2E);
        unpack2(acc1[2], u, v); q.z = bf2(u * L2E, v * L2E);
        unpack2(acc1[3], u, v); q.w = bf2(u * L2E, v * L2E);
        *(uint4*)(g_theta_b + ((size_t)b * NN + n0 + 1) * 8) = q;
    }

    // pool within this row (2 pixels) -> best[40], then combine with partner
    float best[40];
#pragma unroll
    for (int c = 4; c < 24; c++) {
        float u0, v0, u1, v1;
        unpack2(acc0[c], u0, v0);
        unpack2(acc1[c], u1, v1);
        best[2 * c - 8]     = fmaxf(u0, u1);
        best[2 * c - 8 + 1] = fmaxf(v0, v1);
    }
#pragma unroll
    for (int c = 0; c < 40; c++)
        best[c] = fmaxf(best[c], shflx(best[c], 1));   // dy-partner = lane^1

    if (dy == 0) {   // phi bf16 [b][pp][8]
        uint4 q;
        q.x = bf2(best[0], best[1]); q.y = bf2(best[2], best[3]);
        q.z = bf2(best[4], best[5]); q.w = bf2(best[6], best[7]);
        *(uint4*)(g_phi_b + ((size_t)b * NP + pp) * 8) = q;
    } else {         // g transposed bf16 [b][ch][pp]
#pragma unroll
        for (int c = 0; c < 32; c++)
            g_gT_b[((size_t)b * 32 + c) * NP + pp] = __float2bfloat16(best[8 + c]);
    }
}

// =========================================================================
// Kernel 2: mma.sync flash attention + o-projection + residual.
// 512 threads (16 warps). Warp owns 32 queries (2 m16 tiles).
// Mainloop software-pipelined: phi/gB loads for kc+1 rotated ahead, running
// pointers instead of per-load index math.
// =========================================================================
#define THREADS 512
#define NQT 2
#define SM_PHI   0                    // 1024 x 16B bf16        = 16384
#define SM_GB    16384                // 64kc x 4nt x 32 x 8B   = 65536
#define SM_OW    (16384 + 65536)      // 64 x 32 f32            = 8192
#define SM_DEN   (16384 + 65536 + 8192)            // 512 f32   = 2048
#define SM_ATT   (16384 + 65536 + 8192 + 2048)     // 512 x 34 f32 = 69632
#define SMEM_BYTES (16384 + 65536 + 8192 + 2048 + 69632)
#define ATT_STRIDE 34

__global__ void __launch_bounds__(THREADS, 1)
attn_kernel(const float* __restrict__ x,
            const float* __restrict__ ow,
            const float* __restrict__ gamma_p,
            float* __restrict__ out)
{
    extern __shared__ char sm[];
    const int tid  = threadIdx.x;
    const int wid  = tid >> 5;
    const int lane = tid & 31;
    const int g    = lane >> 2;      // groupID
    const int tig  = lane & 3;       // thread-in-group
    const int b    = blockIdx.y;
    const int tile = blockIdx.x;

    // ---- stage phi [key][8ch] bf16 ----
    {
        const uint4* src = (const uint4*)(g_phi_b + (size_t)b * NP * 8);
        uint4* dst = (uint4*)(sm + SM_PHI);
        for (int i = tid; i < 1024; i += THREADS) dst[i] = src[i];
    }
    // ---- stage gB in b-frag order: [kc][nt][lane] = (b0|b1<<32) ----
    {
        const __nv_bfloat16* gT = g_gT_b + (size_t)b * 32 * NP;
        ull* dst = (ull*)(sm + SM_GB);
        for (int idx = tid; idx < 64 * 4 * 32; idx += THREADS) {
            int ln = idx & 31, nt = (idx >> 5) & 3, kc = idx >> 7;
            int ch = nt * 8 + (ln >> 2);
            const __nv_bfloat16* row = gT + (size_t)ch * NP + kc * 16 + 2 * (ln & 3);
            uint lo = *(const uint*)row;        // keys 2tig, 2tig+1
            uint hi = *(const uint*)(row + 8);  // keys 2tig+8, 2tig+9
            dst[idx] = (ull)lo | ((ull)hi << 32);
        }
    }
    // ---- stage ow (f32) ----
    {
        const float4* src = (const float4*)ow;
        float4* dst = (float4*)(sm + SM_OW);
        for (int i = tid; i < 512; i += THREADS) dst[i] = src[i];
    }
    __syncthreads();

    // ---- theta a-frags: NQT q-tiles of 16 rows ----
    const int wq = tile * 512 + wid * (16 * NQT);  // warp's first query (global n)
    uint ta[NQT][2];
#pragma unroll
    for (int qt = 0; qt < NQT; qt++) {
        const __nv_bfloat16* t0 = g_theta_b + ((size_t)b * NN + wq + qt * 16 + g) * 8 + 2 * tig;
        ta[qt][0] = *(const uint*)t0;
        ta[qt][1] = *(const uint*)(t0 + 64);   // row +8 -> +8*8 elements
    }

    float aoc[NQT][4][4];
#pragma unroll
    for (int qt = 0; qt < NQT; qt++)
#pragma unroll
        for (int nt = 0; nt < 4; nt++)
#pragma unroll
            for (int r = 0; r < 4; r++) aoc[qt][nt][r] = 0.f;
    float dn[NQT][2];
#pragma unroll
    for (int qt = 0; qt < NQT; qt++) { dn[qt][0] = 0.f; dn[qt][1] = 0.f; }

    // running pointers (strength-reduced addressing)
    const char* phiP = sm + SM_PHI + g * 16 + tig * 4;   // +256 B per kc; kb offset +128
    const ull*  gP   = (const ull*)(sm + SM_GB) + lane;  // +128 ull per kc; nt offset +32

    // prologue: load kc=0 operands
    uint pb0 = *(const uint*)phiP;
    uint pb1 = *(const uint*)(phiP + 128);
    ull gv0 = gP[0], gv1 = gP[32], gv2 = gP[64], gv3 = gP[96];
    phiP += 256; gP += 128;

    for (int kc = 0; kc < 64; kc++) {
        // rotate: issue kc+1 loads first (latency hidden under this iter's math)
        uint npb0 = *(const uint*)phiP;
        uint npb1 = *(const uint*)(phiP + 128);
        ull ngv0 = gP[0], ngv1 = gP[32], ngv2 = gP[64], ngv3 = gP[96];
        phiP += 256; gP += 128;   // kc=63 prefetch stays in-bounds smem; value discarded

        uint pa[NQT][4];
#pragma unroll
        for (int qt = 0; qt < NQT; qt++) {
            float s[4] = {0.f, 0.f, 0.f, 0.f};
            mma_16n8k8(s, ta[qt], pb0);
            float e0 = ex2f(s[0]), e1 = ex2f(s[1]);
            float e2 = ex2f(s[2]), e3 = ex2f(s[3]);
            dn[qt][0] += e0 + e1;
            dn[qt][1] += e2 + e3;
            pa[qt][0] = bf2(e0, e1);   // (q=g,   k=2tig..+1)
            pa[qt][1] = bf2(e2, e3);   // (q=g+8, k=2tig..+1)
        }
#pragma unroll
        for (int qt = 0; qt < NQT; qt++) {
            float s[4] = {0.f, 0.f, 0.f, 0.f};
            mma_16n8k8(s, ta[qt], pb1);
            float e0 = ex2f(s[0]), e1 = ex2f(s[1]);
            float e2 = ex2f(s[2]), e3 = ex2f(s[3]);
            dn[qt][0] += e0 + e1;
            dn[qt][1] += e2 + e3;
            pa[qt][2] = bf2(e0, e1);
            pa[qt][3] = bf2(e2, e3);
        }
        // GEMM2: A += P x gT  (gv loaded last iteration -> ready)
#pragma unroll
        for (int qt = 0; qt < NQT; qt++) {
            mma_16n8k16(aoc[qt][0], pa[qt], (uint)gv0, (uint)(gv0 >> 32));
            mma_16n8k16(aoc[qt][1], pa[qt], (uint)gv1, (uint)(gv1 >> 32));
            mma_16n8k16(aoc[qt][2], pa[qt], (uint)gv2, (uint)(gv2 >> 32));
            mma_16n8k16(aoc[qt][3], pa[qt], (uint)gv3, (uint)(gv3 >> 32));
        }
        pb0 = npb0; pb1 = npb1;
        gv0 = ngv0; gv1 = ngv1; gv2 = ngv2; gv3 = ngv3;
    }

    // ---- den reduce (over tig lanes) + store attn/den to smem ----
    float* denS = (float*)(sm + SM_DEN);
    float* attS = (float*)(sm + SM_ATT);
    const int wqp = wid * (16 * NQT);          // warp's query offset within tile
#pragma unroll
    for (int qt = 0; qt < NQT; qt++) {
        float d0 = dn[qt][0]; d0 += shflx(d0, 1); d0 += shflx(d0, 2);
        float d1 = dn[qt][1]; d1 += shflx(d1, 1); d1 += shflx(d1, 2);
        if (tig == 0) {
            denS[wqp + qt * 16 + g]     = d0;
            denS[wqp + qt * 16 + g + 8] = d1;
        }
#pragma unroll
        for (int nt = 0; nt < 4; nt++) {
            int q0 = wqp + qt * 16 + g;
            int ch = nt * 8 + 2 * tig;
            *(float2*)(attS + (size_t)q0 * ATT_STRIDE + ch) =
                make_float2(aoc[qt][nt][0], aoc[qt][nt][1]);
            *(float2*)(attS + (size_t)(q0 + 8) * ATT_STRIDE + ch) =
                make_float2(aoc[qt][nt][2], aoc[qt][nt][3]);
        }
    }
    __syncthreads();

    // ---- epilogue: o = ow x attn ; out = (gamma/den) * o + x ----
    const float gamma = *gamma_p;
    const ulonglong2* ow4 = (const ulonglong2*)(sm + SM_OW);   // [j][8]
    {
        const int p = tid;                          // query within tile [0,512)
        ull am[16];
        const ull* ap = (const ull*)(attS + (size_t)p * ATT_STRIDE);
#pragma unroll
        for (int c = 0; c < 16; c++) am[c] = ap[c];
        const float sc = gamma / denS[p];

        const int q = tile * 512 + p;
        const float* xq = x + (size_t)b * CC * NN + q;
        float*       oq = out + (size_t)b * CC * NN + q;
        for (int j = 0; j < 64; j++) {
            const ulonglong2* wj = ow4 + j * 8;
            ulonglong2 w0 = wj[0];
            ull o2 = mul2(w0.x, am[0]);
            fma2(o2, w0.y, am[1]);
#pragma unroll
            for (int k = 1; k < 8; k++) {
                ulonglong2 wk = wj[k];
                fma2(o2, wk.x, am[2 * k]);
                fma2(o2, wk.y, am[2 * k + 1]);
            }
            float oa, ob;
            unpack2(o2, oa, ob);
            oq[(size_t)j * NN] = fmaf(sc, oa + ob, xq[(size_t)j * NN]);
        }
    }
}

// =========================================================================
extern "C" void kernel_launch(void* const* d_in, const int* in_sizes, int n_in,
                              void* d_out, int out_size)
{
    const float* x     = (const float*)d_in[0];
    const float* tw    = (const float*)d_in[1];
    const float* pw    = (const float*)d_in[2];
    const float* gw    = (const float*)d_in[3];
    const float* ow    = (const float*)d_in[4];
    const float* gamma = (const float*)d_in[5];
    float* out = (float*)d_out;

    cudaFuncSetAttribute(attn_kernel,
                         cudaFuncAttributeMaxDynamicSharedMemorySize, SMEM_BYTES);

    proj_kernel<<<BB * NP / 128, 256>>>(x, tw, pw, gw);
    attn_kernel<<<dim3(8, BB), THREADS, SMEM_BYTES>>>(x, ow, gamma, out);
}